// round 8
// baseline (speedup 1.0000x reference)
#include <cuda_runtime.h>
#include <math.h>

// ---------------- problem constants ----------------
#define TT     8192          // batch -> time steps
#define CIN    3
#define IH     23
#define IW     30
#define CO     8
#define OH     22
#define OW     29
#define FEAT   5104          // 8*22*29
#define F1     64
#define SS     32            // sensory size
#define NN     19            // LTC units
#define UNF    6
#define KDIM   5104

// chunk-parallel scan (WARMUP=16 validated in R6: rel_err unchanged)
#define CHUNK  16
#define WARMUP 16
#define NCHUNK (TT / CHUNK)   // 512

// fc1 split-K: slice 0 = k [0,2560), slice 1 = k [2560,5104)
#define KSPLIT 2560

// ---------------- scratch (static device globals; no allocation) ----------------
__device__ float g_y1  [TT * FEAT];    // conv output, flattened (167 MB)
__device__ float g_fc1p[2][TT * F1];   // fc1 K-split partials
__device__ float g_wns[TT * NN];
__device__ float g_wds[TT * NN];

// LTC precomputed params (tanh form), layout [i][j] (source-major)
__device__ float g_A  [NN * NN];     // 0.5*sigma
__device__ float g_Bc [NN * NN];     // -0.5*sigma*mu
__device__ float g_He [NN * NN];     // 0.5*softplus(w)*mask*erev
__device__ float g_Hp [NN * NN];     // 0.5*softplus(w)*mask
__device__ float g_cmt  [NN];        // softplus(cm) * UNF
__device__ float g_baseN[NN];        // g*vleak + sum_i He
__device__ float g_baseD[NN];        // cmt + g + eps + sum_i Hp

// sensory precomputed params
__device__ float g_sA [SS * NN];
__device__ float g_sB [SS * NN];
__device__ float g_sWp[SS * NN];
__device__ float g_sWe[SS * NN];

// ---------------- helpers ----------------
__device__ __forceinline__ float rcpf(float x) {
    float y; asm("rcp.approx.f32 %0, %1;" : "=f"(y) : "f"(x)); return y;
}
__device__ __forceinline__ float tanhaf(float x) {
    float y; asm("tanh.approx.f32 %0, %1;" : "=f"(y) : "f"(x)); return y;
}
__device__ __forceinline__ float softplus_f(float x) {
    return fmaxf(x, 0.0f) + log1pf(expf(-fabsf(x)));
}
// packed dual-FP32 FMA (FFMA2): d = a*b + d per 32-bit half, rn — bit-identical
// to two scalar FFMAs. Only reachable via PTX fma.rn.f32x2.
#define FMA2(d, a, b) \
    asm("fma.rn.f32x2 %0, %1, %2, %0;" : "+l"(d) : "l"(a), "l"(b))

__device__ __forceinline__ float lo_f(unsigned long long p) {
    return __uint_as_float((unsigned)(p & 0xffffffffull));
}
__device__ __forceinline__ float hi_f(unsigned long long p) {
    return __uint_as_float((unsigned)(p >> 32));
}

// ---------------- conv (2x2 valid) + ELU: 1 thread = 1 (b,oh,ow), all 8 co ----
__global__ void __launch_bounds__(256) conv_kernel(const float* __restrict__ x,
                                                   const float* __restrict__ cw,
                                                   const float* __restrict__ cb) {
    __shared__ float wsh[CO * CIN * 4];
    __shared__ float bsh[CO];
    int tid = threadIdx.x;
    if (tid < CO * CIN * 4) wsh[tid] = cw[tid];
    if (tid < CO) bsh[tid] = cb[tid];
    __syncthreads();

    int idx = blockIdx.x * 256 + tid;
    if (idx >= TT * OH * OW) return;
    int b   = idx / (OH * OW);
    int p   = idx - b * (OH * OW);
    int oh  = p / OW;
    int ow_ = p - oh * OW;

    const float* xb = x + (size_t)b * (CIN * IH * IW);
    float in[CIN][2][2];
#pragma unroll
    for (int ci = 0; ci < CIN; ci++)
#pragma unroll
        for (int kh = 0; kh < 2; kh++)
#pragma unroll
            for (int kw = 0; kw < 2; kw++)
                in[ci][kh][kw] = xb[(ci * IH + oh + kh) * IW + ow_ + kw];

    float* yb = g_y1 + (size_t)b * FEAT + p;
#pragma unroll
    for (int co = 0; co < CO; co++) {
        float s = bsh[co];
#pragma unroll
        for (int ci = 0; ci < CIN; ci++)
#pragma unroll
            for (int kh = 0; kh < 2; kh++)
#pragma unroll
                for (int kw = 0; kw < 2; kw++)
                    s = fmaf(in[ci][kh][kw], wsh[((co * CIN + ci) * 2 + kh) * 2 + kw], s);
        yb[co * (OH * OW)] = (s > 0.0f) ? s : expm1f(s);
    }
}

// ---------------- param precompute ----------------
__global__ void prep_kernel(const float* __restrict__ sw,  const float* __restrict__ smu,
                            const float* __restrict__ ssig,const float* __restrict__ serev,
                            const float* __restrict__ smask,
                            const float* __restrict__ w,   const float* __restrict__ mu,
                            const float* __restrict__ sigma,const float* __restrict__ erev,
                            const float* __restrict__ mask,
                            const float* __restrict__ gleak,const float* __restrict__ vleak,
                            const float* __restrict__ cm) {
    const float LOG2E = 1.4426950408889634f;
    int i = threadIdx.x;
    if (i < SS * NN) {
        float W = softplus_f(sw[i]) * smask[i];
        g_sWp[i] = W;
        g_sWe[i] = W * serev[i];
        g_sA[i]  = ssig[i] * LOG2E;
        g_sB[i]  = ssig[i] * smu[i] * LOG2E;
    }
    if (i < NN * NN) {
        float W  = softplus_f(w[i]) * mask[i];
        float Hp = 0.5f * W;
        g_Hp[i] = Hp;
        g_He[i] = Hp * erev[i];
        g_A[i]  = 0.5f * sigma[i];
        g_Bc[i] = -0.5f * sigma[i] * mu[i];
    }
    __syncthreads();
    if (i < NN) {
        int j = i;
        float cN = 0.0f, cD = 0.0f;
        for (int s = 0; s < NN; s++) {
            cN += g_He[s * NN + j];
            cD += g_Hp[s * NN + j];
        }
        float c = softplus_f(cm[j]) * (float)UNF;
        float g = softplus_f(gleak[j]);
        g_cmt  [j] = c;
        g_baseN[j] = g * vleak[j] + cN;
        g_baseD[j] = c + g + 1e-8f + cD;
    }
}

// ---------------- fc1: (T,5104)x(64,5104)^T, K-split, FFMA2 inner ----------------
// blockIdx.x = M tile (64 rows), blockIdx.y = K slice. ReLU deferred to fc2.
// B tile stored DUPLICATED in smem so LDS.128 yields two (b,b) broadcast pairs;
// A pairs come from consecutive M rows. 8 FFMA2 = 16 FMA per thread per kk.
__global__ void __launch_bounds__(256) fc1_kernel(const float* __restrict__ Wg,
                                                  const float* __restrict__ bg) {
    __shared__ float As[16][68];
    __shared__ float Wd[16][136];    // Wd[k][2n] = Wd[k][2n+1] = W[n][k]
    int tid = threadIdx.x;
    int m0  = blockIdx.x * 64;
    int sl  = blockIdx.y;
    int kbeg = sl ? KSPLIT : 0;
    int kend = sl ? KDIM   : KSPLIT;
    int lr  = tid >> 4;         // 0..15
    int lk  = tid & 15;         // 0..15
    int tx  = tid & 15;
    int ty  = tid >> 4;

    unsigned long long acc[2][4] = {};   // [M-pair][N]; pair = rows (ty*4+2p, +1)

    for (int k0 = kbeg; k0 < kend; k0 += 16) {
#pragma unroll
        for (int p = 0; p < 4; p++) {
            int m = lr + 16 * p;
            As[lk][m] = g_y1[(size_t)(m0 + m) * KDIM + k0 + lk];
            float wv  = Wg  [(size_t)m        * KDIM + k0 + lk];
            Wd[lk][2 * m]     = wv;
            Wd[lk][2 * m + 1] = wv;
        }
        __syncthreads();
#pragma unroll
        for (int kk = 0; kk < 16; kk++) {
            ulonglong2 av = *(const ulonglong2*)&As[kk][ty * 4];      // (a0,a1),(a2,a3)
            ulonglong2 b01 = *(const ulonglong2*)&Wd[kk][tx * 8];     // (b0,b0),(b1,b1)
            ulonglong2 b23 = *(const ulonglong2*)&Wd[kk][tx * 8 + 4]; // (b2,b2),(b3,b3)
            FMA2(acc[0][0], av.x, b01.x);
            FMA2(acc[1][0], av.y, b01.x);
            FMA2(acc[0][1], av.x, b01.y);
            FMA2(acc[1][1], av.y, b01.y);
            FMA2(acc[0][2], av.x, b23.x);
            FMA2(acc[1][2], av.y, b23.x);
            FMA2(acc[0][3], av.x, b23.y);
            FMA2(acc[1][3], av.y, b23.y);
        }
        __syncthreads();
    }
#pragma unroll
    for (int pr = 0; pr < 2; pr++)
#pragma unroll
        for (int c = 0; c < 4; c++) {
            int m = m0 + ty * 4 + 2 * pr;
            int n = tx * 4 + c;
            float bias = (sl == 0) ? bg[n] : 0.0f;
            g_fc1p[sl][(m + 0) * F1 + n] = lo_f(acc[pr][c]) + bias;
            g_fc1p[sl][(m + 1) * F1 + n] = hi_f(acc[pr][c]) + bias;
        }
}

// ---------------- fc2 + input map + sensory synapses (fused) ----------------
__global__ void fc2_kernel(const float* __restrict__ W2, const float* __restrict__ b2,
                           const float* __restrict__ iw, const float* __restrict__ ib) {
    __shared__ float Wsh[F1 * SS];
    int tid = threadIdx.x;
    for (int q = tid; q < SS * F1; q += 256) {
        int n = q / F1, k = q - n * F1;
        Wsh[k * SS + n] = W2[q];
    }
    __syncthreads();
    int idx = blockIdx.x * 256 + tid;
    int t = idx >> 5, n = idx & 31;
    const float* r0 = g_fc1p[0] + t * F1;
    const float* r1 = g_fc1p[1] + t * F1;
    float acc = b2[n];
#pragma unroll
    for (int k = 0; k < F1; k++) {
        float h = fmaxf(r0[k] + r1[k], 0.0f);   // ReLU on summed partials
        acc = fmaf(h, Wsh[k * SS + n], acc);
    }
    float sval = fmaf(acc, iw[n], ib[n]);       // seq[t][n]

    int jj = (n < NN) ? n : 0;
    float accN = 0.0f, accD = 0.0f;
#pragma unroll
    for (int i = 0; i < SS; i++) {
        float s = __shfl_sync(0xffffffffu, sval, i);
        float e = exp2f(g_sB[i * NN + jj] - g_sA[i * NN + jj] * s);
        float gate = rcpf(1.0f + e);
        accN = fmaf(g_sWe[i * NN + jj], gate, accN);
        accD = fmaf(g_sWp[i * NN + jj], gate, accD);
    }
    if (n < NN) {
        g_wns[t * NN + n] = accN;
        g_wds[t * NN + n] = accD;
    }
}

// ---------------- LTC scan: chunk-parallel (contractive restart) ----------------
__global__ void __launch_bounds__(32, 1) ltc_kernel(const float* __restrict__ ow,
                                                    const float* __restrict__ ob,
                                                    float* __restrict__ out) {
    int j  = threadIdx.x;
    int jj = (j < NN) ? j : 0;

    float A[NN], B[NN], He[NN], Hp[NN];
#pragma unroll
    for (int i = 0; i < NN; i++) {
        A[i]  = g_A [i * NN + jj];
        B[i]  = g_Bc[i * NN + jj];
        He[i] = g_He[i * NN + jj];
        Hp[i] = g_Hp[i * NN + jj];
    }
    float cmt   = g_cmt  [jj];
    float baseN = g_baseN[jj];
    float baseD = g_baseD[jj];
    float owv = ow[0], obv = ob[0];

    int t0 = blockIdx.x * CHUNK;                  // first emitted step
    int ts = (t0 >= WARMUP) ? (t0 - WARMUP) : 0;  // warm-up start
    int te = t0 + CHUNK;

    float v = 0.0f;
    float wns_c = g_wns[ts * NN + jj];
    float wds_c = g_wds[ts * NN + jj];

    for (int t = ts; t < te; t++) {
        int tn = (t + 1 < te) ? (t + 1) : t;
        float wns_n = g_wns[tn * NN + jj];   // prefetch next step
        float wds_n = g_wds[tn * NN + jj];
        float bN = baseN + wns_c;
        float bD = baseD + wds_c;

#pragma unroll 3
        for (int u = 0; u < UNF; u++) {
            float accN0 = bN, accN1 = 0.0f, accN2 = 0.0f, accN3 = 0.0f;
            float accD0 = bD, accD1 = 0.0f, accD2 = 0.0f, accD3 = 0.0f;
#pragma unroll
            for (int i = 0; i < NN; i++) {
                float vi = __shfl_sync(0xffffffffu, v, i);
                float th = tanhaf(fmaf(A[i], vi, B[i]));
                switch (i & 3) {
                    case 0: accN0 = fmaf(He[i], th, accN0);
                            accD0 = fmaf(Hp[i], th, accD0); break;
                    case 1: accN1 = fmaf(He[i], th, accN1);
                            accD1 = fmaf(Hp[i], th, accD1); break;
                    case 2: accN2 = fmaf(He[i], th, accN2);
                            accD2 = fmaf(Hp[i], th, accD2); break;
                    default:accN3 = fmaf(He[i], th, accN3);
                            accD3 = fmaf(Hp[i], th, accD3); break;
                }
            }
            float wn = (accN0 + accN1) + (accN2 + accN3);
            float wd = (accD0 + accD1) + (accD2 + accD3);
            v = fmaf(cmt, v, wn) * rcpf(wd);
        }
        if (j == 0 && t >= t0) out[t] = fmaf(v, owv, obv);
        wns_c = wns_n;
        wds_c = wds_n;
    }
}

// ---------------- launcher ----------------
extern "C" void kernel_launch(void* const* d_in, const int* in_sizes, int n_in,
                              void* d_out, int out_size) {
    const float* x       = (const float*)d_in[0];
    const float* conv_w  = (const float*)d_in[1];
    const float* conv_b  = (const float*)d_in[2];
    const float* fc1_w   = (const float*)d_in[3];
    const float* fc1_b   = (const float*)d_in[4];
    const float* fc2_w   = (const float*)d_in[5];
    const float* fc2_b   = (const float*)d_in[6];
    const float* input_w = (const float*)d_in[7];
    const float* input_b = (const float*)d_in[8];
    const float* s_w     = (const float*)d_in[9];
    const float* s_mu    = (const float*)d_in[10];
    const float* s_sig   = (const float*)d_in[11];
    const float* s_erev  = (const float*)d_in[12];
    const float* s_mask  = (const float*)d_in[13];
    const float* w_      = (const float*)d_in[14];
    const float* mu_     = (const float*)d_in[15];
    const float* sigma_  = (const float*)d_in[16];
    const float* erev_   = (const float*)d_in[17];
    const float* mask_   = (const float*)d_in[18];
    const float* gleak   = (const float*)d_in[19];
    const float* vleak   = (const float*)d_in[20];
    const float* cm      = (const float*)d_in[21];
    const float* out_w   = (const float*)d_in[22];
    const float* out_b   = (const float*)d_in[23];
    float* out = (float*)d_out;

    conv_kernel<<<(TT * OH * OW + 255) / 256, 256>>>(x, conv_w, conv_b);
    prep_kernel<<<1, 1024>>>(s_w, s_mu, s_sig, s_erev, s_mask,
                             w_, mu_, sigma_, erev_, mask_,
                             gleak, vleak, cm);
    {
        dim3 g(TT / 64, 2);
        fc1_kernel<<<g, 256>>>(fc1_w, fc1_b);
    }
    fc2_kernel<<<(TT * SS) / 256, 256>>>(fc2_w, fc2_b, input_w, input_b);
    ltc_kernel<<<NCHUNK, 32>>>(out_w, out_b, out);
}

// round 9
// speedup vs baseline: 1.7410x; 1.7410x over previous
#include <cuda_runtime.h>
#include <math.h>

// ---------------- problem constants ----------------
#define TT     8192          // batch -> time steps
#define CIN    3
#define IH     23
#define IW     30
#define CO     8
#define OH     22
#define OW     29
#define FEAT   5104          // 8*22*29
#define F1     64
#define SS     32            // sensory size
#define NN     19            // LTC units
#define UNF    6
#define KDIM   5104

// chunk-parallel scan (WARMUP=16 validated in R6: rel_err unchanged)
#define CHUNK  16
#define WARMUP 16
#define NCHUNK (TT / CHUNK)   // 512

// fc1 split-K: slice 0 = k [0,2560), slice 1 = k [2560,5104)
#define KSPLIT 2560

// ---------------- scratch (static device globals; no allocation) ----------------
__device__ float g_y1  [TT * FEAT];    // conv output, flattened (167 MB)
__device__ float g_fc1p[2][TT * F1];   // fc1 K-split partials
__device__ float g_wns[TT * NN];
__device__ float g_wds[TT * NN];

// LTC precomputed params (tanh form), layout [i][j] (source-major)
__device__ float g_A  [NN * NN];     // 0.5*sigma
__device__ float g_Bc [NN * NN];     // -0.5*sigma*mu
__device__ float g_He [NN * NN];     // 0.5*softplus(w)*mask*erev
__device__ float g_Hp [NN * NN];     // 0.5*softplus(w)*mask
__device__ float g_cmt  [NN];        // softplus(cm) * UNF
__device__ float g_baseN[NN];        // g*vleak + sum_i He
__device__ float g_baseD[NN];        // cmt + g + eps + sum_i Hp

// sensory precomputed params
__device__ float g_sA [SS * NN];
__device__ float g_sB [SS * NN];
__device__ float g_sWp[SS * NN];
__device__ float g_sWe[SS * NN];

// ---------------- helpers ----------------
__device__ __forceinline__ float rcpf(float x) {
    float y; asm("rcp.approx.f32 %0, %1;" : "=f"(y) : "f"(x)); return y;
}
__device__ __forceinline__ float tanhaf(float x) {
    float y; asm("tanh.approx.f32 %0, %1;" : "=f"(y) : "f"(x)); return y;
}
__device__ __forceinline__ float softplus_f(float x) {
    return fmaxf(x, 0.0f) + log1pf(expf(-fabsf(x)));
}

// ---------------- conv (2x2 valid) + ELU: 1 thread = 1 (b,oh,ow), all 8 co ----
__global__ void __launch_bounds__(256) conv_kernel(const float* __restrict__ x,
                                                   const float* __restrict__ cw,
                                                   const float* __restrict__ cb) {
    __shared__ float wsh[CO * CIN * 4];
    __shared__ float bsh[CO];
    int tid = threadIdx.x;
    if (tid < CO * CIN * 4) wsh[tid] = cw[tid];
    if (tid < CO) bsh[tid] = cb[tid];
    __syncthreads();

    int idx = blockIdx.x * 256 + tid;
    if (idx >= TT * OH * OW) return;
    int b   = idx / (OH * OW);
    int p   = idx - b * (OH * OW);
    int oh  = p / OW;
    int ow_ = p - oh * OW;

    const float* xb = x + (size_t)b * (CIN * IH * IW);
    float in[CIN][2][2];
#pragma unroll
    for (int ci = 0; ci < CIN; ci++)
#pragma unroll
        for (int kh = 0; kh < 2; kh++)
#pragma unroll
            for (int kw = 0; kw < 2; kw++)
                in[ci][kh][kw] = xb[(ci * IH + oh + kh) * IW + ow_ + kw];

    float* yb = g_y1 + (size_t)b * FEAT + p;
#pragma unroll
    for (int co = 0; co < CO; co++) {
        float s = bsh[co];
#pragma unroll
        for (int ci = 0; ci < CIN; ci++)
#pragma unroll
            for (int kh = 0; kh < 2; kh++)
#pragma unroll
                for (int kw = 0; kw < 2; kw++)
                    s = fmaf(in[ci][kh][kw], wsh[((co * CIN + ci) * 2 + kh) * 2 + kw], s);
        yb[co * (OH * OW)] = (s > 0.0f) ? s : expm1f(s);
    }
}

// ---------------- param precompute ----------------
__global__ void prep_kernel(const float* __restrict__ sw,  const float* __restrict__ smu,
                            const float* __restrict__ ssig,const float* __restrict__ serev,
                            const float* __restrict__ smask,
                            const float* __restrict__ w,   const float* __restrict__ mu,
                            const float* __restrict__ sigma,const float* __restrict__ erev,
                            const float* __restrict__ mask,
                            const float* __restrict__ gleak,const float* __restrict__ vleak,
                            const float* __restrict__ cm) {
    const float LOG2E = 1.4426950408889634f;
    int i = threadIdx.x;
    if (i < SS * NN) {
        float W = softplus_f(sw[i]) * smask[i];
        g_sWp[i] = W;
        g_sWe[i] = W * serev[i];
        g_sA[i]  = ssig[i] * LOG2E;
        g_sB[i]  = ssig[i] * smu[i] * LOG2E;
    }
    if (i < NN * NN) {
        float W  = softplus_f(w[i]) * mask[i];
        float Hp = 0.5f * W;
        g_Hp[i] = Hp;
        g_He[i] = Hp * erev[i];
        g_A[i]  = 0.5f * sigma[i];
        g_Bc[i] = -0.5f * sigma[i] * mu[i];
    }
    __syncthreads();
    if (i < NN) {
        int j = i;
        float cN = 0.0f, cD = 0.0f;
        for (int s = 0; s < NN; s++) {
            cN += g_He[s * NN + j];
            cD += g_Hp[s * NN + j];
        }
        float c = softplus_f(cm[j]) * (float)UNF;
        float g = softplus_f(gleak[j]);
        g_cmt  [j] = c;
        g_baseN[j] = g * vleak[j] + cN;
        g_baseD[j] = c + g + 1e-8f + cD;
    }
}

// ---------------- fc1: (T,5104) x (64,5104)^T, K-split, scalar FFMA ----------------
// blockIdx.x = M tile (64 rows), blockIdx.y = K slice. ReLU deferred to fc2.
__global__ void __launch_bounds__(256) fc1_kernel(const float* __restrict__ Wg,
                                                  const float* __restrict__ bg) {
    __shared__ float As[16][68];
    __shared__ float Ws[16][68];
    int tid = threadIdx.x;
    int m0  = blockIdx.x * 64;
    int sl  = blockIdx.y;
    int kbeg = sl ? KSPLIT : 0;
    int kend = sl ? KDIM   : KSPLIT;
    int lr  = tid >> 4;
    int lk  = tid & 15;
    int tx  = tid & 15;
    int ty  = tid >> 4;
    float acc[4][4] = {};

    for (int k0 = kbeg; k0 < kend; k0 += 16) {
#pragma unroll
        for (int p = 0; p < 4; p++) {
            int m = lr + 16 * p;
            As[lk][m] = g_y1[(size_t)(m0 + m) * KDIM + k0 + lk];
            Ws[lk][m] = Wg  [(size_t)m        * KDIM + k0 + lk];
        }
        __syncthreads();
#pragma unroll
        for (int kk = 0; kk < 16; kk++) {
            float4 a = *(const float4*)&As[kk][ty * 4];
            float4 b = *(const float4*)&Ws[kk][tx * 4];
            acc[0][0] = fmaf(a.x, b.x, acc[0][0]);
            acc[0][1] = fmaf(a.x, b.y, acc[0][1]);
            acc[0][2] = fmaf(a.x, b.z, acc[0][2]);
            acc[0][3] = fmaf(a.x, b.w, acc[0][3]);
            acc[1][0] = fmaf(a.y, b.x, acc[1][0]);
            acc[1][1] = fmaf(a.y, b.y, acc[1][1]);
            acc[1][2] = fmaf(a.y, b.z, acc[1][2]);
            acc[1][3] = fmaf(a.y, b.w, acc[1][3]);
            acc[2][0] = fmaf(a.z, b.x, acc[2][0]);
            acc[2][1] = fmaf(a.z, b.y, acc[2][1]);
            acc[2][2] = fmaf(a.z, b.z, acc[2][2]);
            acc[2][3] = fmaf(a.z, b.w, acc[2][3]);
            acc[3][0] = fmaf(a.w, b.x, acc[3][0]);
            acc[3][1] = fmaf(a.w, b.y, acc[3][1]);
            acc[3][2] = fmaf(a.w, b.z, acc[3][2]);
            acc[3][3] = fmaf(a.w, b.w, acc[3][3]);
        }
        __syncthreads();
    }
#pragma unroll
    for (int r = 0; r < 4; r++)
#pragma unroll
        for (int c = 0; c < 4; c++) {
            int m = m0 + ty * 4 + r;
            int n = tx * 4 + c;
            float v = acc[r][c] + (sl == 0 ? bg[n] : 0.0f);
            g_fc1p[sl][m * F1 + n] = v;
        }
}

// ---------------- fc2 + input map + sensory synapses (fused) ----------------
__global__ void fc2_kernel(const float* __restrict__ W2, const float* __restrict__ b2,
                           const float* __restrict__ iw, const float* __restrict__ ib) {
    __shared__ float Wsh[F1 * SS];
    int tid = threadIdx.x;
    for (int q = tid; q < SS * F1; q += 256) {
        int n = q / F1, k = q - n * F1;
        Wsh[k * SS + n] = W2[q];
    }
    __syncthreads();
    int idx = blockIdx.x * 256 + tid;
    int t = idx >> 5, n = idx & 31;
    const float* r0 = g_fc1p[0] + t * F1;
    const float* r1 = g_fc1p[1] + t * F1;
    float acc = b2[n];
#pragma unroll
    for (int k = 0; k < F1; k++) {
        float h = fmaxf(r0[k] + r1[k], 0.0f);   // ReLU on summed partials
        acc = fmaf(h, Wsh[k * SS + n], acc);
    }
    float sval = fmaf(acc, iw[n], ib[n]);       // seq[t][n]

    int jj = (n < NN) ? n : 0;
    float accN = 0.0f, accD = 0.0f;
#pragma unroll
    for (int i = 0; i < SS; i++) {
        float s = __shfl_sync(0xffffffffu, sval, i);
        float e = exp2f(g_sB[i * NN + jj] - g_sA[i * NN + jj] * s);
        float gate = rcpf(1.0f + e);
        accN = fmaf(g_sWe[i * NN + jj], gate, accN);
        accD = fmaf(g_sWp[i * NN + jj], gate, accD);
    }
    if (n < NN) {
        g_wns[t * NN + n] = accN;
        g_wds[t * NN + n] = accD;
    }
}

// ---------------- LTC scan: chunk-parallel (contractive restart) ----------------
__global__ void __launch_bounds__(32, 1) ltc_kernel(const float* __restrict__ ow,
                                                    const float* __restrict__ ob,
                                                    float* __restrict__ out) {
    int j  = threadIdx.x;
    int jj = (j < NN) ? j : 0;

    float A[NN], B[NN], He[NN], Hp[NN];
#pragma unroll
    for (int i = 0; i < NN; i++) {
        A[i]  = g_A [i * NN + jj];
        B[i]  = g_Bc[i * NN + jj];
        He[i] = g_He[i * NN + jj];
        Hp[i] = g_Hp[i * NN + jj];
    }
    float cmt   = g_cmt  [jj];
    float baseN = g_baseN[jj];
    float baseD = g_baseD[jj];
    float owv = ow[0], obv = ob[0];

    int t0 = blockIdx.x * CHUNK;                  // first emitted step
    int ts = (t0 >= WARMUP) ? (t0 - WARMUP) : 0;  // warm-up start
    int te = t0 + CHUNK;

    float v = 0.0f;
    float wns_c = g_wns[ts * NN + jj];
    float wds_c = g_wds[ts * NN + jj];

    for (int t = ts; t < te; t++) {
        int tn = (t + 1 < te) ? (t + 1) : t;
        float wns_n = g_wns[tn * NN + jj];   // prefetch next step
        float wds_n = g_wds[tn * NN + jj];
        float bN = baseN + wns_c;
        float bD = baseD + wds_c;

#pragma unroll 3
        for (int u = 0; u < UNF; u++) {
            float accN0 = bN, accN1 = 0.0f, accN2 = 0.0f, accN3 = 0.0f;
            float accD0 = bD, accD1 = 0.0f, accD2 = 0.0f, accD3 = 0.0f;
#pragma unroll
            for (int i = 0; i < NN; i++) {
                float vi = __shfl_sync(0xffffffffu, v, i);
                float th = tanhaf(fmaf(A[i], vi, B[i]));
                switch (i & 3) {
                    case 0: accN0 = fmaf(He[i], th, accN0);
                            accD0 = fmaf(Hp[i], th, accD0); break;
                    case 1: accN1 = fmaf(He[i], th, accN1);
                            accD1 = fmaf(Hp[i], th, accD1); break;
                    case 2: accN2 = fmaf(He[i], th, accN2);
                            accD2 = fmaf(Hp[i], th, accD2); break;
                    default:accN3 = fmaf(He[i], th, accN3);
                            accD3 = fmaf(Hp[i], th, accD3); break;
                }
            }
            float wn = (accN0 + accN1) + (accN2 + accN3);
            float wd = (accD0 + accD1) + (accD2 + accD3);
            v = fmaf(cmt, v, wn) * rcpf(wd);
        }
        if (j == 0 && t >= t0) out[t] = fmaf(v, owv, obv);
        wns_c = wns_n;
        wds_c = wds_n;
    }
}

// ---------------- launcher ----------------
extern "C" void kernel_launch(void* const* d_in, const int* in_sizes, int n_in,
                              void* d_out, int out_size) {
    const float* x       = (const float*)d_in[0];
    const float* conv_w  = (const float*)d_in[1];
    const float* conv_b  = (const float*)d_in[2];
    const float* fc1_w   = (const float*)d_in[3];
    const float* fc1_b   = (const float*)d_in[4];
    const float* fc2_w   = (const float*)d_in[5];
    const float* fc2_b   = (const float*)d_in[6];
    const float* input_w = (const float*)d_in[7];
    const float* input_b = (const float*)d_in[8];
    const float* s_w     = (const float*)d_in[9];
    const float* s_mu    = (const float*)d_in[10];
    const float* s_sig   = (const float*)d_in[11];
    const float* s_erev  = (const float*)d_in[12];
    const float* s_mask  = (const float*)d_in[13];
    const float* w_      = (const float*)d_in[14];
    const float* mu_     = (const float*)d_in[15];
    const float* sigma_  = (const float*)d_in[16];
    const float* erev_   = (const float*)d_in[17];
    const float* mask_   = (const float*)d_in[18];
    const float* gleak   = (const float*)d_in[19];
    const float* vleak   = (const float*)d_in[20];
    const float* cm      = (const float*)d_in[21];
    const float* out_w   = (const float*)d_in[22];
    const float* out_b   = (const float*)d_in[23];
    float* out = (float*)d_out;

    conv_kernel<<<(TT * OH * OW + 255) / 256, 256>>>(x, conv_w, conv_b);
    prep_kernel<<<1, 1024>>>(s_w, s_mu, s_sig, s_erev, s_mask,
                             w_, mu_, sigma_, erev_, mask_,
                             gleak, vleak, cm);
    {
        dim3 g(TT / 64, 2);
        fc1_kernel<<<g, 256>>>(fc1_w, fc1_b);
    }
    fc2_kernel<<<(TT * SS) / 256, 256>>>(fc2_w, fc2_b, input_w, input_b);
    ltc_kernel<<<NCHUNK, 32>>>(out_w, out_b, out);
}